// round 16
// baseline (speedup 1.0000x reference)
#include <cuda_runtime.h>
#include <cuda_fp16.h>
#include <cstdint>

#define IN_      512
#define OUT_     512
#define NB_      16
#define M_TOTAL  1024
#define TM       32
#define TN       32
#define NTHREADS 128
#define NCHUNK   8              // k-chunks of 64 fp16

#define X_ELEMS  (M_TOTAL * IN_)      // 524,288
#define XCONV_BLOCKS (X_ELEMS / 8 / 256)   // 256

// smem: A chunk planes [0,32K), B chunk planes [32K,64K). 4KB per plane.
#define PLANE      4096
#define A_OFFB(c)  ((uint32_t)(c) * PLANE)
#define B_OFFB(c)  (32768u + (uint32_t)(c) * PLANE)
#define SMEM_TOTAL 65536

// device globals: fp16 x + global binning plan
__device__ __align__(16) __half g_x16[X_ELEMS];
__device__ int g_rows[NB_ * M_TOTAL];
__device__ int g_cnt[NB_];

// ---------------- PTX helpers ----------------
__device__ __forceinline__ uint32_t smem_u32(const void* p) {
    uint32_t a;
    asm("{ .reg .u64 t; cvta.to.shared.u64 t, %1; cvt.u32.u64 %0, t; }" : "=r"(a) : "l"(p));
    return a;
}
__device__ __forceinline__ void ldsm4(uint32_t* r, uint32_t addr) {
    asm volatile("ldmatrix.sync.aligned.m8n8.x4.shared.b16 {%0,%1,%2,%3}, [%4];"
        : "=r"(r[0]), "=r"(r[1]), "=r"(r[2]), "=r"(r[3]) : "r"(addr));
}
__device__ __forceinline__ void mma_fp16(float* c, const uint32_t* a, uint32_t b0, uint32_t b1) {
    asm volatile("mma.sync.aligned.m16n8k16.row.col.f32.f16.f16.f32 "
        "{%0,%1,%2,%3}, {%4,%5,%6,%7}, {%8,%9}, {%0,%1,%2,%3};"
        : "+f"(c[0]), "+f"(c[1]), "+f"(c[2]), "+f"(c[3])
        : "r"(a[0]), "r"(a[1]), "r"(a[2]), "r"(a[3]), "r"(b0), "r"(b1));
}
__device__ __forceinline__ void cp_async16(uint32_t dst, const void* src, int srcsize) {
    asm volatile("cp.async.cg.shared.global [%0], [%1], 16, %2;"
        :: "r"(dst), "l"(src), "r"(srcsize) : "memory");
}
#define CP_COMMIT() asm volatile("cp.async.commit_group;" ::: "memory")

__device__ __forceinline__ uint32_t h2bits(__half2 h) {
    return *reinterpret_cast<uint32_t*>(&h);
}
__device__ __forceinline__ uint4 pack8(float4 a, float4 b) {
    uint4 o;
    o.x = h2bits(__floats2half2_rn(a.x, a.y));
    o.y = h2bits(__floats2half2_rn(a.z, a.w));
    o.z = h2bits(__floats2half2_rn(b.x, b.y));
    o.w = h2bits(__floats2half2_rn(b.z, b.w));
    return o;
}

// ---------------- prep: x -> fp16; block 256 bins rows ----------------
__global__ __launch_bounds__(256) void prep_kernel(
    const float* __restrict__ x, const int* __restrict__ sel)
{
    if (blockIdx.x == XCONV_BLOCKS) {
        // global order-free binning plan (row results are order-independent)
        int tid = threadIdx.x;
        if (tid < NB_) g_cnt[tid] = 0;
        __syncthreads();
        #pragma unroll
        for (int i = 0; i < M_TOTAL / 256; i++) {
            int idx = tid + i * 256;
            int g = sel[idx];
            int p = atomicAdd(&g_cnt[g], 1);
            g_rows[g * M_TOTAL + p] = idx;
        }
        return;
    }
    size_t i = ((size_t)blockIdx.x * 256 + threadIdx.x) * 8;
    float4 a = *(const float4*)(x + i);
    float4 b = *(const float4*)(x + i + 4);
    *(uint4*)(g_x16 + i) = pack8(a, b);
}

// compute one 64-k chunk (T literal); B is smem-resident
#define COMPUTE_CHUNK(T) do {                                                  \
    const uint32_t a_b = sm_b + A_OFFB(T) + a_off;                             \
    const uint32_t b_b = sm_b + B_OFFB(T) + b_off;                             \
    _Pragma("unroll")                                                          \
    for (int s = 0; s < 4; s++) {                                              \
        uint32_t koff = ((uint32_t)(khalf + s * 32)) ^ swx;                    \
        uint32_t ah[4], bh[4];                                                 \
        ldsm4(ah, a_b + koff);                                                 \
        ldsm4(bh, b_b + koff);                                                 \
        mma_fp16(acc[0], ah, bh[0], bh[2]);                                    \
        mma_fp16(acc[1], ah, bh[1], bh[3]);                                    \
    }                                                                          \
} while (0)

#define PIPE_STEP(TT, WAITN) do {                                              \
    asm volatile("cp.async.wait_group %0;" :: "n"(WAITN) : "memory");          \
    __syncthreads();                                                           \
    COMPUTE_CHUNK(2 * (TT));                                                   \
    COMPUTE_CHUNK(2 * (TT) + 1);                                               \
} while (0)

// ---------------- grouped GEMM: B resident in smem, A via cp.async ----------
__global__ __launch_bounds__(NTHREADS, 3) void gemm_kernel(
    const float* __restrict__ w,      // (NB, OUT, IN) fp32
    const float* __restrict__ bias,   // (NB, OUT)
    float* __restrict__ out)          // (1024, OUT)
{
    extern __shared__ __align__(128) uint8_t smem[];

    const int tid = threadIdx.x;
    const int lid = tid & 31, wid = tid >> 5;
    const int warp_m = wid & 1;        // 2 m-warps x 16 rows
    const int warp_n = wid >> 1;       // 2 n-warps x 16 cols
    const int g  = blockIdx.y;
    const int n0 = blockIdx.x * TN;

    const int cnt = g_cnt[g];
    const uint32_t sm_b = smem_u32(smem);

    // staging geometry (R14/R15-verified): row = tid>>2, two 16B units
    const int st_row = tid >> 2;                 // 0..31
    const int u0     = (tid & 3) * 2;            // 16B units
    const uint32_t st_msk = (uint32_t)(st_row & 7) << 4;
    const uint32_t dst0 = ((uint32_t)(st_row * 128 + u0 * 16))       ^ st_msk;
    const uint32_t dst1 = ((uint32_t)(st_row * 128 + (u0 + 1) * 16)) ^ st_msk;

    // prefetch this thread's A row ids for all m-passes (cnt <= 128 w.h.p.;
    // loop below still guards with (mrow < cnt))
    int rr[4];
    #pragma unroll
    for (int j = 0; j < 4; j++) {
        int mrow = j * TM + st_row;
        rr[j] = (mrow < cnt) ? g_rows[g * M_TOTAL + mrow] : 0;
    }

    // ---- issue m-pass-0 A prologue FIRST (streams under the B convert) ----
    {
        const __half* a_src = g_x16 + (size_t)rr[0] * IN_ + u0 * 8;
        const int asz = (st_row < cnt) ? 16 : 0;
        #pragma unroll
        for (int c = 0; c < NCHUNK; c++) {
            cp_async16(sm_b + A_OFFB(c) + dst0, a_src + c * 64,     asz);
            cp_async16(sm_b + A_OFFB(c) + dst1, a_src + c * 64 + 8, asz);
            CP_COMMIT();
        }
    }

    // ---- convert this CTA's B tile ONCE: 32 rows x K=512 fp32 -> fp16 smem ----
    {
        const float* __restrict__ bsrc =
            w + ((size_t)g * OUT_ + n0 + st_row) * IN_ + u0 * 8;
        #pragma unroll
        for (int c = 0; c < NCHUNK; c++) {
            const float* s = bsrc + c * 64;
            float4 v0 = *(const float4*)(s);
            float4 v1 = *(const float4*)(s + 4);
            float4 v2 = *(const float4*)(s + 8);
            float4 v3 = *(const float4*)(s + 12);
            *(uint4*)(smem + B_OFFB(c) + dst0) = pack8(v0, v1);
            *(uint4*)(smem + B_OFFB(c) + dst1) = pack8(v2, v3);
        }
    }

    // ldmatrix constant address parts (R13-R15-verified)
    const uint32_t swx   = (uint32_t)(lid & 7) * 16;
    const uint32_t khalf = (uint32_t)(lid >> 4) * 16;
    const uint32_t a_off = (uint32_t)(warp_m * 16 + (lid & 15)) * 128;
    const uint32_t b_off = (uint32_t)(warp_n * 16 + (lid & 15)) * 128;

    #pragma unroll 1
    for (int mp = 0; mp * TM < cnt; mp++) {
        const int m0 = mp * TM;

        // m-passes >= 1: A prologue (buffers freed by trailing barrier)
        if (mp > 0) {
            const __half* a_src = g_x16 + (size_t)rr[mp & 3] * IN_ + u0 * 8;
            const int asz = (m0 + st_row < cnt) ? 16 : 0;
            #pragma unroll
            for (int c = 0; c < NCHUNK; c++) {
                cp_async16(sm_b + A_OFFB(c) + dst0, a_src + c * 64,     asz);
                cp_async16(sm_b + A_OFFB(c) + dst1, a_src + c * 64 + 8, asz);
                CP_COMMIT();
            }
        }

        float acc[2][4] = {};
        PIPE_STEP(0, 6);    // barrier also publishes the B tile (mp==0)
        PIPE_STEP(1, 4);
        PIPE_STEP(2, 2);
        PIPE_STEP(3, 0);

        // ---- epilogue: scatter rows with bias ----
        {
            int gq = lid >> 2, tq = lid & 3;
            int m_lo = m0 + warp_m * 16 + gq;
            int r0 = (m_lo     < cnt) ? g_rows[g * M_TOTAL + m_lo]     : -1;
            int r1 = (m_lo + 8 < cnt) ? g_rows[g * M_TOTAL + m_lo + 8] : -1;
            #pragma unroll
            for (int nf = 0; nf < 2; nf++) {
                int col = warp_n * 16 + nf * 8 + tq * 2;
                float2 bb = *(const float2*)&bias[g * OUT_ + n0 + col];
                if (r0 >= 0) {
                    float2 v = make_float2(acc[nf][0] + bb.x, acc[nf][1] + bb.y);
                    *(float2*)&out[(size_t)r0 * OUT_ + n0 + col] = v;
                }
                if (r1 >= 0) {
                    float2 v = make_float2(acc[nf][2] + bb.x, acc[nf][3] + bb.y);
                    *(float2*)&out[(size_t)r1 * OUT_ + n0 + col] = v;
                }
            }
        }
        __syncthreads();   // A buffers fully consumed before next prologue
    }
}

// ---------------------------------------------------------------------------
extern "C" void kernel_launch(void* const* d_in, const int* in_sizes, int n_in,
                              void* d_out, int out_size) {
    const float* tensor = (const float*)d_in[0];   // (B,S,K,IN) fp32
    const int*   sel    = (const int*)  d_in[1];   // (B,S,K) int32
    const float* weight = (const float*)d_in[2];   // (NB,OUT,IN) fp32
    const float* bias   = (const float*)d_in[3];   // (NB,OUT) fp32
    float*       out    = (float*)d_out;           // (B,S,K,OUT) fp32

    cudaFuncSetAttribute(gemm_kernel, cudaFuncAttributeMaxDynamicSharedMemorySize, SMEM_TOTAL);
    prep_kernel<<<XCONV_BLOCKS + 1, 256>>>(tensor, sel);       // ~0.8 us
    dim3 grid(OUT_ / TN, NB_);   // (16, 16) = 256 CTAs, single wave @ 2/SM
    gemm_kernel<<<grid, NTHREADS, SMEM_TOTAL>>>(weight, bias, out);
}